// round 1
// baseline (speedup 1.0000x reference)
#include <cuda_runtime.h>
#include <math.h>

#define B_ 4
#define A_ 16
#define N_ 8
#define L_ 512
#define NL_ 4096
#define DE_ 256
#define DH_ 64
#define H_ 8
#define DHEAD_ 32

// Scratch (allocation-free rule: __device__ globals)
__device__ float g_qW[B_ * A_ * H_ * DE_];     // 512 KB, L2-resident
__device__ float g_vals[B_ * NL_ * DH_];       // 4 MB
__device__ float g_mh[B_ * H_ * A_ * DH_];     // 128 KB

__device__ __forceinline__ float warp_sum(float v) {
    v += __shfl_xor_sync(0xffffffffu, v, 16);
    v += __shfl_xor_sync(0xffffffffu, v, 8);
    v += __shfl_xor_sync(0xffffffffu, v, 4);
    v += __shfl_xor_sync(0xffffffffu, v, 2);
    v += __shfl_xor_sync(0xffffffffu, v, 1);
    return v;
}

// ============================================================================
// K1: q = LN(curr_rho) @ Wq.T ; qW[b,a,h,e] = (1/sqrt(32)) * sum_d q[h*32+d]*Wk[h*32+d,e]
// grid 64 = (b,a), 256 threads. Also zeros g_mh.
// ============================================================================
__global__ void k_qw(const float* __restrict__ curr, const float* __restrict__ Wq,
                     const float* __restrict__ Wk, const float* __restrict__ lnw,
                     const float* __restrict__ lnb)
{
    __shared__ float sred[256];
    __shared__ float sln[DE_];
    __shared__ float sq[DE_];
    const int ba = blockIdx.x, tid = threadIdx.x;
    float x = curr[ba * DE_ + tid];

    sred[tid] = x; __syncthreads();
    for (int s = 128; s > 0; s >>= 1) { if (tid < s) sred[tid] += sred[tid + s]; __syncthreads(); }
    float mu = sred[0] * (1.0f / DE_);
    __syncthreads();
    float d = x - mu;
    sred[tid] = d * d; __syncthreads();
    for (int s = 128; s > 0; s >>= 1) { if (tid < s) sred[tid] += sred[tid + s]; __syncthreads(); }
    float var = sred[0] * (1.0f / DE_);
    float ln = d * rsqrtf(var + 1e-5f) * lnw[tid] + lnb[tid];
    sln[tid] = ln; __syncthreads();

    float acc = 0.f;
    for (int e = 0; e < DE_; e++) acc += sln[e] * Wq[tid * DE_ + e];
    sq[tid] = acc; __syncthreads();

    const float scale = rsqrtf((float)DHEAD_);
    for (int h = 0; h < H_; h++) {
        float v = 0.f;
        for (int dd = 0; dd < DHEAD_; dd++)
            v += sq[h * DHEAD_ + dd] * Wk[(h * DHEAD_ + dd) * DE_ + tid];
        g_qW[(ba * H_ + h) * DE_ + tid] = v * scale;
    }
    // zero m_h accumulator (32768 elems, 16384 threads -> 2 each)
    for (int i = ba * 256 + tid; i < B_ * H_ * A_ * DH_; i += 64 * 256) g_mh[i] = 0.f;
}

// ============================================================================
// K2: scores[b,h,a,x] = LN(rho[b,x,a,:]) . qW[b,a,h,:]  (scale folded into qW)
// Warp per row, 32 rows/warp (same (b,a)), qW register-resident, prefetched loads.
// score(h,j) parked in lane j -> coalesced 128B stores at the end.
// grid 1024 x 256 threads = 8192 warps = 64 (b,a) x 128 chunks.
// ============================================================================
__global__ void __launch_bounds__(256) k_scores(
    const float* __restrict__ rho, const int* __restrict__ mask,
    const float* __restrict__ lnw, const float* __restrict__ lnb,
    float* __restrict__ attn)
{
    const int warp = threadIdx.x >> 5, lane = threadIdx.x & 31;
    const int gw = blockIdx.x * 8 + warp;
    const int ba = gw >> 7;              // 128 chunks per (b,a)
    const int chunk = gw & 127;
    const int b = ba >> 4, a = ba & 15;
    const int x0 = chunk << 5;

    float4 qw0[H_], qw1[H_];
#pragma unroll
    for (int h = 0; h < H_; h++) {
        const float4* p = (const float4*)(g_qW + (ba * H_ + h) * DE_);
        qw0[h] = p[lane];
        qw1[h] = p[32 + lane];
    }
    const float4 w0 = ((const float4*)lnw)[lane], w1 = ((const float4*)lnw)[32 + lane];
    const float4 e0 = ((const float4*)lnb)[lane], e1 = ((const float4*)lnb)[32 + lane];
    const int mymask = mask[b * NL_ + x0 + lane];

    const float* base = rho + ((size_t)(b * NL_ + x0) * A_ + a) * DE_;
    const size_t rstride = (size_t)A_ * DE_;
    float4 c0 = ((const float4*)base)[lane];
    float4 c1 = ((const float4*)base)[32 + lane];

    float s[H_];
#pragma unroll 4
    for (int j = 0; j < 32; j++) {
        const float4 r0 = c0, r1 = c1;
        if (j < 31) {  // software prefetch next row
            const float4* nb = (const float4*)(base + (size_t)(j + 1) * rstride);
            c0 = nb[lane]; c1 = nb[32 + lane];
        }
        float sum = r0.x + r0.y + r0.z + r0.w + r1.x + r1.y + r1.z + r1.w;
        float ssq = r0.x * r0.x + r0.y * r0.y + r0.z * r0.z + r0.w * r0.w
                  + r1.x * r1.x + r1.y * r1.y + r1.z * r1.z + r1.w * r1.w;
        sum = warp_sum(sum); ssq = warp_sum(ssq);
        const float mu = sum * (1.0f / DE_);
        const float inv = rsqrtf(ssq * (1.0f / DE_) - mu * mu + 1e-5f);

        const float l0 = (r0.x - mu) * inv * w0.x + e0.x;
        const float l1 = (r0.y - mu) * inv * w0.y + e0.y;
        const float l2 = (r0.z - mu) * inv * w0.z + e0.z;
        const float l3 = (r0.w - mu) * inv * w0.w + e0.w;
        const float l4 = (r1.x - mu) * inv * w1.x + e1.x;
        const float l5 = (r1.y - mu) * inv * w1.y + e1.y;
        const float l6 = (r1.z - mu) * inv * w1.z + e1.z;
        const float l7 = (r1.w - mu) * inv * w1.w + e1.w;

        float acc[H_];
#pragma unroll
        for (int h = 0; h < H_; h++) {
            acc[h] = l0 * qw0[h].x + l1 * qw0[h].y + l2 * qw0[h].z + l3 * qw0[h].w
                   + l4 * qw1[h].x + l5 * qw1[h].y + l6 * qw1[h].z + l7 * qw1[h].w;
        }
#pragma unroll
        for (int h = 0; h < H_; h++) acc[h] = warp_sum(acc[h]);
        const int mj = __shfl_sync(0xffffffffu, mymask, j);
        if (lane == j) {
#pragma unroll
            for (int h = 0; h < H_; h++) s[h] = mj ? acc[h] : -INFINITY;
        }
    }
#pragma unroll
    for (int h = 0; h < H_; h++)
        attn[((size_t)(b * H_ + h) * A_ + a) * NL_ + x0 + lane] = s[h];
}

// ============================================================================
// K3: vals_tan0 = logmap0(demo_hyp, c=1). Warp per 64-elem row, 16384 rows.
// ============================================================================
__global__ void __launch_bounds__(256) k_vals(const float* __restrict__ hyp)
{
    const int warp = threadIdx.x >> 5, lane = threadIdx.x & 31;
    const int gw = blockIdx.x * 8 + warp;   // 2048 blocks * 8 = 16384 rows
    const float2 v = ((const float2*)(hyp + (size_t)gw * DH_))[lane];
    float nn = warp_sum(v.x * v.x + v.y * v.y);
    float n = fmaxf(sqrtf(nn), 1e-15f);
    float u = fminf(n, 1.0f - 1e-5f);
    float f = atanhf(u) / n;
    float2 o; o.x = v.x * f; o.y = v.y * f;
    ((float2*)(g_vals + (size_t)gw * DH_))[lane] = o;
}

// ============================================================================
// K4: in-place softmax over each 4096-length row of attn. Block per row (512).
// ============================================================================
__global__ void __launch_bounds__(256) k_softmax(float* __restrict__ attn)
{
    __shared__ float sm[NL_];
    __shared__ float sp[8];
    const int tid = threadIdx.x, warp = tid >> 5, lane = tid & 31;
    float* p = attn + (size_t)blockIdx.x * NL_;

    float mx = -INFINITY;
    for (int i = tid; i < NL_; i += 256) { float v = p[i]; sm[i] = v; mx = fmaxf(mx, v); }
    for (int o = 16; o > 0; o >>= 1) mx = fmaxf(mx, __shfl_xor_sync(0xffffffffu, mx, o));
    if (lane == 0) sp[warp] = mx;
    __syncthreads();
    mx = sp[0];
#pragma unroll
    for (int w = 1; w < 8; w++) mx = fmaxf(mx, sp[w]);
    __syncthreads();

    float sum = 0.f;
    for (int i = tid; i < NL_; i += 256) { float e = expf(sm[i] - mx); sm[i] = e; sum += e; }
    sum = warp_sum(sum);
    if (lane == 0) sp[warp] = sum;
    __syncthreads();
    float tot = sp[0];
#pragma unroll
    for (int w = 1; w < 8; w++) tot += sp[w];
    const float invs = 1.0f / tot;
    for (int i = tid; i < NL_; i += 256) p[i] = sm[i] * invs;
}

// ============================================================================
// K5: m_h[b,h,a,d] = sum_x attn[b,h,a,x] * vals[b,x,d]. smem-tiled,
// grid (B,H,8 x-splits) = 256 blocks, atomicAdd partials into zeroed g_mh.
// ============================================================================
__global__ void __launch_bounds__(256) k_mh(const float* __restrict__ attn)
{
    __shared__ float sv[64][65];
    __shared__ float sa[16][64];
    const int b = blockIdx.x, h = blockIdx.y, xs = blockIdx.z;
    const int tid = threadIdx.x;
    const int d = tid & 63, rq = tid >> 6;   // rq in 0..3, owns rows rq*4..rq*4+3
    float acc[4] = {0.f, 0.f, 0.f, 0.f};

    for (int c = 0; c < 8; c++) {
        const int xb = xs * 512 + c * 64;
        for (int idx = tid; idx < 4096; idx += 256) {
            int xx = idx >> 6, dd = idx & 63;
            sv[xx][dd] = g_vals[((size_t)(b * NL_ + xb + xx)) * DH_ + dd];
        }
        for (int idx = tid; idx < 1024; idx += 256) {
            int rr = idx >> 6, xx = idx & 63;
            sa[rr][xx] = attn[((size_t)((b * H_ + h) * A_ + rr)) * NL_ + xb + xx];
        }
        __syncthreads();
#pragma unroll 8
        for (int x = 0; x < 64; x++) {
            const float v = sv[x][d];
#pragma unroll
            for (int q = 0; q < 4; q++) acc[q] += sa[rq * 4 + q][x] * v;
        }
        __syncthreads();
    }
#pragma unroll
    for (int q = 0; q < 4; q++) {
        const int aa = rq * 4 + q;
        atomicAdd(&g_mh[((size_t)(b * H_ + h) * A_ + aa) * DH_ + d], acc[q]);
    }
}

// ============================================================================
// K6: tail — y = logmap0(expmap0(m_h)); mean over h; expmap0; radius clamp;
// mean over a -> curr_hyp[b, 0:64]. Block per b, 8 warps (each warp: 2 a's).
// ============================================================================
__global__ void __launch_bounds__(256) k_tail(float* __restrict__ out)
{
    __shared__ float shyp[A_][DH_];
    const int b = blockIdx.x;
    const int warp = threadIdx.x >> 5, lane = threadIdx.x & 31;

    for (int ai = 0; ai < 2; ai++) {
        const int a = warp + ai * 8;
        float t0 = 0.f, t1 = 0.f;
        for (int h = 0; h < H_; h++) {
            const float2 m = ((const float2*)(g_mh + ((size_t)(b * H_ + h) * A_ + a) * DH_))[lane];
            float nn = warp_sum(m.x * m.x + m.y * m.y);
            float n = fmaxf(sqrtf(nn), 1e-15f);
            float ce = tanhf(n) / n;                 // expmap0 coefficient
            float ex = m.x * ce, ey = m.y * ce;
            float nn2 = warp_sum(ex * ex + ey * ey);
            float n2 = fmaxf(sqrtf(nn2), 1e-15f);
            float u = fminf(n2, 1.0f - 1e-5f);
            float f = atanhf(u) / n2;                // logmap0 coefficient
            t0 += ex * f; t1 += ey * f;
        }
        t0 *= (1.0f / H_); t1 *= (1.0f / H_);
        float nn = warp_sum(t0 * t0 + t1 * t1);
        float n = fmaxf(sqrtf(nn), 1e-15f);
        float ce = tanhf(n) / n;                     // expmap0
        float cx = t0 * ce, cy = t1 * ce;
        float nn2 = warp_sum(cx * cx + cy * cy);
        float nc = fmaxf(sqrtf(nn2), 1e-6f);
        float sc = fminf((1.0f - 1e-5f) / nc, 1.0f); // max_rad = 1/sqrt(C)-1e-5
        shyp[a][lane * 2] = cx * sc;
        shyp[a][lane * 2 + 1] = cy * sc;
    }
    __syncthreads();
    if (threadIdx.x < DH_) {
        float s = 0.f;
        for (int a = 0; a < A_; a++) s += shyp[a][threadIdx.x];
        out[b * DH_ + threadIdx.x] = s * (1.0f / A_);
    }
}

// ============================================================================
extern "C" void kernel_launch(void* const* d_in, const int* in_sizes, int n_in,
                              void* d_out, int out_size)
{
    const float* curr = (const float*)d_in[0];
    const float* rho  = (const float*)d_in[1];
    const float* hyp  = (const float*)d_in[2];
    const int*   mask = (const int*)d_in[3];
    const float* Wq   = (const float*)d_in[4];
    const float* Wk   = (const float*)d_in[5];
    const float* lqw  = (const float*)d_in[6];
    const float* lqb  = (const float*)d_in[7];
    const float* lkw  = (const float*)d_in[8];
    const float* lkb  = (const float*)d_in[9];

    float* out  = (float*)d_out;
    float* attn = out + B_ * DH_;   // curr_hyp first (256 floats), then attn (B,H,A,N,L)

    k_qw<<<64, 256>>>(curr, Wq, Wk, lqw, lqb);
    k_scores<<<1024, 256>>>(rho, mask, lkw, lkb, attn);
    k_vals<<<2048, 256>>>(hyp);
    k_softmax<<<512, 256>>>(attn);
    dim3 g5(B_, H_, 8);
    k_mh<<<g5, 256>>>(attn);
    k_tail<<<B_, 256>>>(out);
}

// round 2
// speedup vs baseline: 1.2890x; 1.2890x over previous
#include <cuda_runtime.h>
#include <math.h>

#define FULLMASK 0xffffffffu
#define B_ 4
#define A_ 16
#define NL_ 4096
#define DE_ 256
#define DH_ 64
#define H_ 8

// Scratch (__device__ globals; allocation-free rule)
__device__ float g_qW[64 * H_ * DE_];     // wq = lnkw ⊙ qW, per (ba,h)
__device__ float g_c[64 * 16];            // c1[ba][h], c2[ba][h]
__device__ float g_vals[B_ * NL_ * DH_];  // logmap0(demo_hyp)
__device__ float g_mh[B_ * H_ * A_ * DH_];

__device__ __forceinline__ float warp_sum(float v) {
    v += __shfl_xor_sync(FULLMASK, v, 16);
    v += __shfl_xor_sync(FULLMASK, v, 8);
    v += __shfl_xor_sync(FULLMASK, v, 4);
    v += __shfl_xor_sync(FULLMASK, v, 2);
    v += __shfl_xor_sync(FULLMASK, v, 1);
    return v;
}

// ============================================================================
// K1 (merged prep): blocks 0..63 -> qW/c1/c2; blocks 64..2111 -> vals + zero mh
// ============================================================================
__global__ void __launch_bounds__(256) k_prep(
    const float* __restrict__ curr, const float* __restrict__ Wq,
    const float* __restrict__ Wk, const float* __restrict__ lqw,
    const float* __restrict__ lqb, const float* __restrict__ lkw,
    const float* __restrict__ lkb, const float* __restrict__ hyp)
{
    const int tid = threadIdx.x;
    if (blockIdx.x >= 64) {
        // logmap0(demo_hyp): warp per 64-elem row; also zero g_mh
        const int bi = blockIdx.x - 64;
        const int warp = tid >> 5, lane = tid & 31;
        const int gw = bi * 8 + warp;    // 0..16383 rows
        const float2 v = ((const float2*)(hyp + (size_t)gw * DH_))[lane];
        float nn = v.x * v.x + v.y * v.y;
        nn = warp_sum(nn);
        float n = fmaxf(sqrtf(nn), 1e-15f);
        float u = fminf(n, 1.0f - 1e-5f);
        float f = atanhf(u) / n;
        float2 o; o.x = v.x * f; o.y = v.y * f;
        ((float2*)(g_vals + (size_t)gw * DH_))[lane] = o;
        const int idx = bi * 256 + tid;
        if (idx < B_ * H_ * A_ * DH_) g_mh[idx] = 0.f;
        return;
    }
    __shared__ float sred[256];
    __shared__ float sln[256];
    __shared__ float sq[256];
    const int ba = blockIdx.x;
    float x = curr[ba * 256 + tid];
    sred[tid] = x; __syncthreads();
    for (int s = 128; s > 0; s >>= 1) { if (tid < s) sred[tid] += sred[tid + s]; __syncthreads(); }
    float mu = sred[0] * (1.f / 256.f); __syncthreads();
    float d = x - mu;
    sred[tid] = d * d; __syncthreads();
    for (int s = 128; s > 0; s >>= 1) { if (tid < s) sred[tid] += sred[tid + s]; __syncthreads(); }
    float var = sred[0] * (1.f / 256.f);
    sln[tid] = d * rsqrtf(var + 1e-5f) * lqw[tid] + lqb[tid];
    __syncthreads();

    float acc = 0.f;
    const float4* wr = (const float4*)(Wq + tid * 256);
    const float4* lr = (const float4*)sln;
#pragma unroll 8
    for (int i = 0; i < 64; i++) {
        float4 w = wr[i]; float4 l = lr[i];
        acc += w.x * l.x + w.y * l.y + w.z * l.z + w.w * l.w;
    }
    sq[tid] = acc; __syncthreads();

    const float scale = 0.17677669529663689f;  // 1/sqrt(32)
    const float mw = lkw[tid], mb = lkb[tid];
    for (int h = 0; h < 8; h++) {
        float v = 0.f;
#pragma unroll
        for (int dd = 0; dd < 32; dd++)
            v += sq[h * 32 + dd] * Wk[(h * 32 + dd) * 256 + tid];
        v *= scale;
        float wqv = v * mw;                      // lnkw folded in
        g_qW[(ba * 8 + h) * 256 + tid] = wqv;
        // c1[h] = sum_e wq[e]
        sred[tid] = wqv; __syncthreads();
        for (int s = 128; s > 0; s >>= 1) { if (tid < s) sred[tid] += sred[tid + s]; __syncthreads(); }
        if (tid == 0) g_c[ba * 16 + h] = sred[0];
        __syncthreads();
        // c2[h] = sum_e lnkb[e]*qw[e]
        sred[tid] = v * mb; __syncthreads();
        for (int s = 128; s > 0; s >>= 1) { if (tid < s) sred[tid] += sred[tid + s]; __syncthreads(); }
        if (tid == 0) g_c[ba * 16 + 8 + h] = sred[0];
        __syncthreads();
    }
}

// ============================================================================
// K2: scores. Warp per row; algebraic LN fold; single batched multi-value
// shuffle reduction (15 shfl/row); 2-row-deep prefetch; smem tile staging
// for coalesced stores.
// ============================================================================
#define MERGE(out, lo, hi, pd, dd) { \
    float _sel = (pd) ? (hi) : (lo); \
    float _oth = (pd) ? (lo) : (hi); \
    out = _sel + __shfl_xor_sync(FULLMASK, _oth, dd); }

__device__ __forceinline__ void process_row(
    const float4 r0, const float4 r1, const int j,
    const int lane, const bool pb1, const bool pb2, const bool pb4,
    const float4* __restrict__ qw0, const float4* __restrict__ qw1,
    const float myc1, const float myc2, float* __restrict__ stw)
{
    float sum = ((r0.x + r0.y) + (r0.z + r0.w)) + ((r1.x + r1.y) + (r1.z + r1.w));
    float ssq = r0.x * r0.x;
    ssq = fmaf(r0.y, r0.y, ssq); ssq = fmaf(r0.z, r0.z, ssq); ssq = fmaf(r0.w, r0.w, ssq);
    ssq = fmaf(r1.x, r1.x, ssq); ssq = fmaf(r1.y, r1.y, ssq);
    ssq = fmaf(r1.z, r1.z, ssq); ssq = fmaf(r1.w, r1.w, ssq);

    float acc[8];
#pragma unroll
    for (int h = 0; h < 8; h++) {
        float t = r0.x * qw0[h].x;
        t = fmaf(r0.y, qw0[h].y, t); t = fmaf(r0.z, qw0[h].z, t); t = fmaf(r0.w, qw0[h].w, t);
        t = fmaf(r1.x, qw1[h].x, t); t = fmaf(r1.y, qw1[h].y, t);
        t = fmaf(r1.z, qw1[h].z, t); t = fmaf(r1.w, qw1[h].w, t);
        acc[h] = t;
    }
    // interleaved multi-value reduction: lane ends holding acc[lane&7] (full)
    float m0, m1, m2, m3, n0, n1, p;
    MERGE(m0, acc[0], acc[1], pb1, 1); MERGE(m1, acc[2], acc[3], pb1, 1);
    MERGE(m2, acc[4], acc[5], pb1, 1); MERGE(m3, acc[6], acc[7], pb1, 1);
    MERGE(n0, m0, m1, pb2, 2); MERGE(n1, m2, m3, pb2, 2);
    MERGE(p, n0, n1, pb4, 4);
    p += __shfl_xor_sync(FULLMASK, p, 8);
    p += __shfl_xor_sync(FULLMASK, p, 16);
    // sum/ssq pair reduction
    float t; MERGE(t, sum, ssq, pb1, 1);
    t += __shfl_xor_sync(FULLMASK, t, 2);
    t += __shfl_xor_sync(FULLMASK, t, 4);
    t += __shfl_xor_sync(FULLMASK, t, 8);
    t += __shfl_xor_sync(FULLMASK, t, 16);
    float o = __shfl_xor_sync(FULLMASK, t, 1);
    float sT = pb1 ? o : t;
    float qT = pb1 ? t : o;
    float mu  = sT * (1.f / 256.f);
    float inv = rsqrtf(fmaf(-mu, mu, qT * (1.f / 256.f)) + 1e-5f);
    float sc  = fmaf(inv, fmaf(-mu, myc1, p), myc2);
    if (lane < 8) stw[lane * 33 + j] = sc;
}

__global__ void __launch_bounds__(256, 2) k_scores(
    const float* __restrict__ rho, const int* __restrict__ mask,
    float* __restrict__ attn)
{
    __shared__ float stile[8][8 * 33];
    const int warp = threadIdx.x >> 5, lane = threadIdx.x & 31;
    const int gw = blockIdx.x * 8 + warp;
    const int ba = gw >> 7, chunk = gw & 127;
    const int b = ba >> 4, a = ba & 15;
    const int x0 = chunk << 5;

    float4 qw0[8], qw1[8];
#pragma unroll
    for (int h = 0; h < 8; h++) {
        const float4* p = (const float4*)(g_qW + (ba * 8 + h) * 256);
        qw0[h] = p[lane]; qw1[h] = p[32 + lane];
    }
    const float myc1 = g_c[ba * 16 + (lane & 7)];
    const float myc2 = g_c[ba * 16 + 8 + (lane & 7)];
    const int mymask = mask[b * NL_ + x0 + lane];
    const bool pb1 = lane & 1, pb2 = lane & 2, pb4 = lane & 4;
    float* stw = &stile[warp][0];

    const float* base = rho + ((size_t)(b * NL_ + x0) * 16 + a) * 256;
    const float4* r;
    r = (const float4*)base;          float4 A0 = r[lane], A1 = r[32 + lane];
    r = (const float4*)(base + 4096); float4 B0 = r[lane], B1 = r[32 + lane];

#pragma unroll 1
    for (int jj = 0; jj < 16; jj++) {
        const int j0 = jj * 2;
        float4 c0 = A0, c1 = A1;
        if (j0 < 30) { r = (const float4*)(base + (size_t)(j0 + 2) * 4096); A0 = r[lane]; A1 = r[32 + lane]; }
        float4 d0 = B0, d1 = B1;
        if (j0 < 29) { r = (const float4*)(base + (size_t)(j0 + 3) * 4096); B0 = r[lane]; B1 = r[32 + lane]; }
        process_row(c0, c1, j0,     lane, pb1, pb2, pb4, qw0, qw1, myc1, myc2, stw);
        process_row(d0, d1, j0 + 1, lane, pb1, pb2, pb4, qw0, qw1, myc1, myc2, stw);
    }
    __syncwarp();
#pragma unroll
    for (int h = 0; h < 8; h++) {
        float v = stw[h * 33 + lane];
        attn[((size_t)((b * 8 + h) * 16 + a)) * NL_ + x0 + lane] = mymask ? v : -INFINITY;
    }
}

// ============================================================================
// K3: softmax, register-resident float4 per thread, 1024 threads/block
// ============================================================================
__global__ void __launch_bounds__(1024) k_softmax(float* __restrict__ attn)
{
    __shared__ float sred[32];
    const int tid = threadIdx.x, lane = tid & 31, wid = tid >> 5;
    float4* p = (float4*)(attn + (size_t)blockIdx.x * NL_);
    float4 v = p[tid];
    float mx = fmaxf(fmaxf(v.x, v.y), fmaxf(v.z, v.w));
    for (int d = 16; d; d >>= 1) mx = fmaxf(mx, __shfl_xor_sync(FULLMASK, mx, d));
    if (lane == 0) sred[wid] = mx;
    __syncthreads();
    if (wid == 0) {
        float m = sred[lane];
        for (int d = 16; d; d >>= 1) m = fmaxf(m, __shfl_xor_sync(FULLMASK, m, d));
        if (lane == 0) sred[0] = m;
    }
    __syncthreads();
    mx = sred[0];
    __syncthreads();
    v.x = __expf(v.x - mx); v.y = __expf(v.y - mx);
    v.z = __expf(v.z - mx); v.w = __expf(v.w - mx);
    float s = (v.x + v.y) + (v.z + v.w);
    for (int d = 16; d; d >>= 1) s += __shfl_xor_sync(FULLMASK, s, d);
    if (lane == 0) sred[wid] = s;
    __syncthreads();
    if (wid == 0) {
        float m = sred[lane];
        for (int d = 16; d; d >>= 1) m += __shfl_xor_sync(FULLMASK, m, d);
        if (lane == 0) sred[0] = m;
    }
    __syncthreads();
    const float inv = 1.0f / sred[0];
    v.x *= inv; v.y *= inv; v.z *= inv; v.w *= inv;
    p[tid] = v;
}

// ============================================================================
// K5: m_h = attn @ vals, smem-tiled, x-split + atomicAdd partials
// ============================================================================
__global__ void __launch_bounds__(256) k_mh(const float* __restrict__ attn)
{
    __shared__ float sv[64][65];
    __shared__ float sa[16][64];
    const int b = blockIdx.x, h = blockIdx.y, xs = blockIdx.z;
    const int tid = threadIdx.x;
    const int d = tid & 63, rq = tid >> 6;
    float acc[4] = {0.f, 0.f, 0.f, 0.f};

    for (int c = 0; c < 8; c++) {
        const int xb = xs * 512 + c * 64;
        for (int idx = tid; idx < 4096; idx += 256) {
            int xx = idx >> 6, dd = idx & 63;
            sv[xx][dd] = g_vals[((size_t)(b * NL_ + xb + xx)) * DH_ + dd];
        }
        for (int idx = tid; idx < 1024; idx += 256) {
            int rr = idx >> 6, xx = idx & 63;
            sa[rr][xx] = attn[((size_t)((b * H_ + h) * 16 + rr)) * NL_ + xb + xx];
        }
        __syncthreads();
#pragma unroll 8
        for (int x = 0; x < 64; x++) {
            const float v = sv[x][d];
#pragma unroll
            for (int q = 0; q < 4; q++) acc[q] += sa[rq * 4 + q][x] * v;
        }
        __syncthreads();
    }
#pragma unroll
    for (int q = 0; q < 4; q++) {
        const int aa = rq * 4 + q;
        atomicAdd(&g_mh[((size_t)(b * H_ + h) * 16 + aa) * DH_ + d], acc[q]);
    }
}

// ============================================================================
// K6: tail — log/exp maps, means, radius clamp
// ============================================================================
__global__ void __launch_bounds__(256) k_tail(float* __restrict__ out)
{
    __shared__ float shyp[16][DH_];
    const int b = blockIdx.x;
    const int warp = threadIdx.x >> 5, lane = threadIdx.x & 31;

    for (int ai = 0; ai < 2; ai++) {
        const int a = warp + ai * 8;
        float t0 = 0.f, t1 = 0.f;
        for (int h = 0; h < H_; h++) {
            const float2 m = ((const float2*)(g_mh + ((size_t)(b * H_ + h) * 16 + a) * DH_))[lane];
            float nn = warp_sum(m.x * m.x + m.y * m.y);
            float n = fmaxf(sqrtf(nn), 1e-15f);
            float ce = tanhf(n) / n;
            float ex = m.x * ce, ey = m.y * ce;
            float nn2 = warp_sum(ex * ex + ey * ey);
            float n2 = fmaxf(sqrtf(nn2), 1e-15f);
            float u = fminf(n2, 1.0f - 1e-5f);
            float f = atanhf(u) / n2;
            t0 += ex * f; t1 += ey * f;
        }
        t0 *= (1.0f / H_); t1 *= (1.0f / H_);
        float nn = warp_sum(t0 * t0 + t1 * t1);
        float n = fmaxf(sqrtf(nn), 1e-15f);
        float ce = tanhf(n) / n;
        float cx = t0 * ce, cy = t1 * ce;
        float nn2 = warp_sum(cx * cx + cy * cy);
        float nc = fmaxf(sqrtf(nn2), 1e-6f);
        float sc = fminf((1.0f - 1e-5f) / nc, 1.0f);
        shyp[a][lane * 2] = cx * sc;
        shyp[a][lane * 2 + 1] = cy * sc;
    }
    __syncthreads();
    if (threadIdx.x < DH_) {
        float s = 0.f;
        for (int a = 0; a < 16; a++) s += shyp[a][threadIdx.x];
        out[b * DH_ + threadIdx.x] = s * (1.0f / 16.0f);
    }
}

// ============================================================================
extern "C" void kernel_launch(void* const* d_in, const int* in_sizes, int n_in,
                              void* d_out, int out_size)
{
    const float* curr = (const float*)d_in[0];
    const float* rho  = (const float*)d_in[1];
    const float* hyp  = (const float*)d_in[2];
    const int*   mask = (const int*)d_in[3];
    const float* Wq   = (const float*)d_in[4];
    const float* Wk   = (const float*)d_in[5];
    const float* lqw  = (const float*)d_in[6];
    const float* lqb  = (const float*)d_in[7];
    const float* lkw  = (const float*)d_in[8];
    const float* lkb  = (const float*)d_in[9];

    float* out  = (float*)d_out;
    float* attn = out + B_ * DH_;

    k_prep<<<2112, 256>>>(curr, Wq, Wk, lqw, lqb, lkw, lkb, hyp);
    k_scores<<<1024, 256>>>(rho, mask, attn);
    k_softmax<<<512, 1024>>>(attn);
    dim3 g5(B_, H_, 8);
    k_mh<<<g5, 256>>>(attn);
    k_tail<<<B_, 256>>>(out);
}